// round 8
// baseline (speedup 1.0000x reference)
#include <cuda_runtime.h>

#define NN 2000
#define KX 16
#define CH 16
#define NODE_TILE 4096
#define SPAD 20

// ---------------- device scratch (static globals: allocation-free) ----------
__device__ int g_nbrs[NN * KX];
__device__ __align__(16) float g_F1[(size_t)NN * NODE_TILE];  // 32 MB
__device__ double g_gsum[48];

// ---------------- shared layout for the step kernel -------------------------
// sp arrays use a swizzled padded layout: logical A[x][y][c] stored at
// sp[arr][x][y ^ x][c] with row pad SPAD=20 floats. Both A[al][be] and
// A[be][al] then land on physical column (al^be) -> identical, well-spread
// bank pattern for the transposed read in phase B.
struct Sm {
    float tile[4][NODE_TILE];     // phase A: 4 F[j] tiles; phase B: 4 partial acc buffers [csec][pos*16+h]
    float sp[6][KX][KX][SPAD];    // 0:s0 1:s1 2:s2 3:d0 4:d1 5:d2 (swizzled)
    float W[16][288];
    float v0[KX][CH];
    float v1p[4][KX][CH];
    float v2p[4][KX][CH];
    float rowt[KX][16];
    float colt[KX][16];
    float bb[16];
    float red[32][16];
    int nbrs_i[KX];
    int nbrs_j[4][KX];
    int pi[4][KX];
};

__device__ __forceinline__ unsigned long long ld2(const float* p) {
    return *reinterpret_cast<const unsigned long long*>(p);
}
#define FMA2(acc, x, y) \
    asm("fma.rn.f32x2 %0, %1, %2, %3;" : "=l"(acc) : "l"(x), "l"(y), "l"(acc))

// ---------------- kernel 1: neighbor extraction + zero g --------------------
__global__ void nbrs_kernel(const float* __restrict__ adj) {
    if (blockIdx.x == 0 && threadIdx.x < 48) g_gsum[threadIdx.x] = 0.0;
    int w = blockIdx.x * (blockDim.x >> 5) + (threadIdx.x >> 5);
    int lane = threadIdx.x & 31;
    if (w >= NN) return;
    const float* row = adj + (size_t)w * NN;
    int cnt = 0;
    for (int base = 0; base < NN; base += 32) {
        int col = base + lane;
        float v = (col < NN) ? row[col] : 0.f;
        unsigned mask = __ballot_sync(0xffffffffu, v > 0.5f);
        if (v > 0.5f) {
            int pos = cnt + __popc(mask & ((1u << lane) - 1u));
            if (pos < KX) g_nbrs[w * KX + pos] = col;
        }
        cnt += __popc(mask);
    }
}

// ---------------- kernel 2: F0 channel sums ---------------------------------
__global__ void f0sum_kernel(const float* __restrict__ X) {
    int idx = blockIdx.x * 256 + threadIdx.x;
    float loc[16];
#pragma unroll
    for (int c = 0; c < 16; ++c) loc[c] = 0.f;
    if (idx < NN * KX) {
        int node = g_nbrs[idx];
#pragma unroll
        for (int c = 0; c < 16; ++c) loc[c] = X[node * 16 + c];
    }
#pragma unroll
    for (int c = 0; c < 16; ++c) {
        float v = loc[c];
#pragma unroll
        for (int o = 16; o; o >>= 1) v += __shfl_xor_sync(0xffffffffu, v, o);
        loc[c] = v;
    }
    __shared__ float sh[8][16];
    int wid = threadIdx.x >> 5, lane = threadIdx.x & 31;
    if (lane == 0) {
#pragma unroll
        for (int c = 0; c < 16; ++c) sh[wid][c] = loc[c];
    }
    __syncthreads();
    if (threadIdx.x < 16) {
        float s = 0.f;
#pragma unroll
        for (int w = 0; w < 8; ++w) s += sh[w][threadIdx.x];
        atomicAdd(&g_gsum[threadIdx.x], (double)s);
    }
}

// ---------------- kernel 3/4: one CCN step ----------------------------------
// 1024 threads = 4 groups x 256. Group g handles m = iter*4+g.
template <int MODE>
__global__ __launch_bounds__(1024, 1) void step_kernel(
    const float* __restrict__ X, const float* __restrict__ Wg,
    const float* __restrict__ bg) {
    extern __shared__ char smraw[];
    Sm* sm = reinterpret_cast<Sm*>(smraw);
    const int i = blockIdx.x;
    const int tid = threadIdx.x;
    const int g = tid >> 8, t = tid & 255;
    const int xa = t >> 4, c = t & 15;

    if (tid < 16) sm->nbrs_i[tid] = g_nbrs[i * KX + tid];
    for (int idx = tid; idx < 16 * 288; idx += 1024) (&sm->W[0][0])[idx] = Wg[idx];
    if (tid >= 32 && tid < 48) sm->bb[tid - 32] = bg[tid - 32];
    __syncthreads();

    // ---------------- Phase A ------------------------------------------------
    float s0r[16];
#pragma unroll
    for (int b = 0; b < 16; ++b) s0r[b] = 0.f;
    float v1acc = 0.f, v2acc = 0.f;

    for (int iter = 0; iter < 4; ++iter) {
        const int m = iter * 4 + g;
        const int j = sm->nbrs_i[m];
        if (t < 16) {
            sm->nbrs_j[g][t] = g_nbrs[j * KX + t];
            __syncwarp(0x0000FFFFu);
            int tgt = sm->nbrs_i[t];
            int p = -1;
#pragma unroll
            for (int q = 0; q < 16; ++q)
                if (sm->nbrs_j[g][q] == tgt) p = q;
            sm->pi[g][t] = p;
        }
        if (MODE == 2) {
            const float4* src = (const float4*)(g_F1 + (size_t)j * NODE_TILE);
            float4* dst = (float4*)&sm->tile[g][0];
#pragma unroll
            for (int r = 0; r < 4; ++r) dst[t + 256 * r] = src[t + 256 * r];
        }
        __syncthreads();

        const int pa = sm->pi[g][xa];
        if (MODE == 1) {
            // F0[j] is diagonal: T_m[a,b,c] = (a==b) * X[nbrs_j[pi[a]], c]
            float xv = (pa >= 0) ? X[sm->nbrs_j[g][pa] * CH + c] : 0.f;
            s0r[xa] += xv;
            v1acc += xv;
            v2acc += xv;
            float dv = (xa == m) ? xv : 0.f;
            sm->sp[1][m][xa ^ m][c] = xv;   // s1[m][b]
            sm->sp[2][m][xa ^ m][c] = xv;   // s2[m][a]
            sm->sp[3][m][xa ^ m][c] = dv;   // d0[m][b]
            sm->sp[4][m][xa ^ m][c] = dv;   // d1[m][a]
            sm->sp[5][m][xa ^ m][c] = xv;   // d2[m][y]
        } else {
            const float* tg = &sm->tile[g][0];
            float rowSum = 0.f;
#pragma unroll
            for (int b = 0; b < 16; ++b) {
                int pb = sm->pi[g][b];
                float v = 0.f;
                if (pa >= 0 && pb >= 0) v = tg[pa * 256 + pb * 16 + c];
                s0r[b] += v;
                rowSum += v;
                if (b == m) sm->sp[4][m][xa ^ m][c] = v;   // d1[m][a] = T[a][m]
                if (b == xa) sm->sp[5][m][xa ^ m][c] = v;  // d2[m][y] = T[y][y]
                if (xa == m) sm->sp[3][m][b ^ m][c] = v;   // d0[m][b] = T[m][b]
            }
            sm->sp[2][m][xa ^ m][c] = rowSum;  // s2[m][a] = sum_b
            v1acc += rowSum;
            float colSum = 0.f;
            if (pa >= 0) {
#pragma unroll
                for (int a2 = 0; a2 < 16; ++a2) {
                    int p2 = sm->pi[g][a2];
                    if (p2 >= 0) colSum += tg[p2 * 256 + pa * 16 + c];
                }
            }
            sm->sp[1][m][xa ^ m][c] = colSum;  // s1[m][b] = sum_a
            v2acc += colSum;
        }
        __syncthreads();
        if (t < 16) {  // v0[m][c] = sum_a s2[m][a][c]
            float s = 0.f;
#pragma unroll
            for (int a2 = 0; a2 < 16; ++a2) s += sm->sp[2][m][a2 ^ m][t];
            sm->v0[m][t] = s;
        }
    }

    // s0 partials (registers -> tile buffers), v1/v2 partials
#pragma unroll
    for (int b = 0; b < 16; ++b) sm->tile[g][xa * 256 + b * 16 + c] = s0r[b];
    sm->v1p[g][xa][c] = v1acc;
    sm->v2p[g][xa][c] = v2acc;
    __syncthreads();
    // combine s0 into swizzled sp[0]
    for (int idx = tid; idx < NODE_TILE; idx += 1024) {
        int a2 = idx >> 8, b2 = (idx >> 4) & 15, c2 = idx & 15;
        float s = sm->tile[0][idx] + sm->tile[1][idx] + sm->tile[2][idx] +
                  sm->tile[3][idx];
        sm->sp[0][a2][b2 ^ a2][c2] = s;
    }
    __syncthreads();

    // ---------------- Phase B ------------------------------------------------
    // row/col broadcast terms (blocks 12..17)
    if (tid < 512) {
        const int half = tid >> 8;  // 0 -> rowt (even blocks), 1 -> colt (odd)
        const int al = (tid >> 4) & 15, h = tid & 15;
        const int off = half * 16;
        float acc = 0.f;
#pragma unroll
        for (int cc = 0; cc < 16; ++cc) {
            float a0 = sm->v0[al][cc];
            float a1 = sm->v1p[0][al][cc] + sm->v1p[1][al][cc] +
                       sm->v1p[2][al][cc] + sm->v1p[3][al][cc];
            float a2v = sm->v2p[0][al][cc] + sm->v2p[1][al][cc] +
                        sm->v2p[2][al][cc] + sm->v2p[3][al][cc];
            acc += a0 * sm->W[h][192 + off + cc] + a1 * sm->W[h][224 + off + cc] +
                   a2v * sm->W[h][256 + off + cc];
        }
        if (half == 0) sm->rowt[al][h] = acc;
        else           sm->colt[al][h] = acc;
    }

    // warp-GEMM: warp w -> 32 positions (pb block) x channel section csec.
    const int w = tid >> 5, lane = tid & 31;
    const int posb = (w & 7) * 32 + lane;
    const int alp = posb >> 4, bep = posb & 15;
    const int csec = w >> 3;
    const int colsw = alp ^ bep;  // swizzled physical column for BOTH va & vb
    unsigned long long acc2[16];
#pragma unroll
    for (int h = 0; h < 16; ++h) acc2[h] = 0ull;

#pragma unroll 2
    for (int u = 0; u < 12; ++u) {
        int kp = csec * 12 + u;          // 48 channel-pairs total
        int arr = kp >> 3;
        int cc = (kp & 7) * 2;
        const float* base = &sm->sp[arr][0][0][0];
        unsigned long long va2 = ld2(base + (alp * 16 + colsw) * SPAD + cc);
        unsigned long long vb2 = ld2(base + (bep * 16 + colsw) * SPAD + cc);
        const float* wp = &sm->W[0][arr * 32 + cc];
#pragma unroll
        for (int h = 0; h < 16; ++h) {
            unsigned long long we2 = ld2(wp + h * 288);       // uniform -> bcast
            unsigned long long wo2 = ld2(wp + h * 288 + 16);
            FMA2(acc2[h], va2, we2);
            FMA2(acc2[h], vb2, wo2);
        }
    }
    // unpack + store channel-section partials into tile[csec]
    {
        float* part = &sm->tile[csec][0];
#pragma unroll
        for (int h = 0; h < 16; ++h) {
            float lo = __uint_as_float((unsigned)acc2[h]);
            float hi = __uint_as_float((unsigned)(acc2[h] >> 32));
            part[posb * 16 + h] = lo + hi;
        }
    }
    __syncthreads();

    // final combine: thread -> (pos, h-quad)
    const int pos = tid >> 2, hq = tid & 3;
    const int alf = pos >> 4, bef = pos & 15;
    float vals[4];
#pragma unroll
    for (int k2 = 0; k2 < 4; ++k2) {
        int h = hq * 4 + k2;
        int idx = pos * 16 + h;
        float v = sm->tile[0][idx] + sm->tile[1][idx] + sm->tile[2][idx] +
                  sm->tile[3][idx] + sm->bb[h] + sm->rowt[alf][h] +
                  sm->colt[bef][h];
        vals[k2] = fmaxf(v, 0.f);
    }
    if (MODE == 1) {
        float4* out = (float4*)(g_F1 + (size_t)i * NODE_TILE + pos * 16 + hq * 4);
        *out = make_float4(vals[0], vals[1], vals[2], vals[3]);
    }
    // g reduction: sum over positions (lane bits 2..4 hold pos&7)
#pragma unroll
    for (int k2 = 0; k2 < 4; ++k2) {
        float v = vals[k2];
        v += __shfl_xor_sync(0xffffffffu, v, 4);
        v += __shfl_xor_sync(0xffffffffu, v, 8);
        v += __shfl_xor_sync(0xffffffffu, v, 16);
        vals[k2] = v;
    }
    if (lane < 4) {
#pragma unroll
        for (int k2 = 0; k2 < 4; ++k2) sm->red[w][lane * 4 + k2] = vals[k2];
    }
    __syncthreads();
    if (tid < 16) {
        float s = 0.f;
#pragma unroll
        for (int w2 = 0; w2 < 32; ++w2) s += sm->red[w2][tid];
        atomicAdd(&g_gsum[(MODE == 1 ? 16 : 32) + tid], (double)s);
    }
}

// ---------------- kernel 5: final dot with fc --------------------------------
__global__ void final_kernel(const float* __restrict__ fc_w,
                             const float* __restrict__ fc_b,
                             float* __restrict__ out) {
    if (threadIdx.x == 0) {
        double s = (double)fc_b[0];
#pragma unroll
        for (int c = 0; c < 48; ++c) s += g_gsum[c] * (double)fc_w[c];
        out[0] = (float)s;
    }
}

// ---------------- host entry --------------------------------------------------
extern "C" void kernel_launch(void* const* d_in, const int* in_sizes, int n_in,
                              void* d_out, int out_size) {
    const float* X   = (const float*)d_in[0];
    const float* adj = (const float*)d_in[1];
    const float* W1  = (const float*)d_in[2];
    const float* b1  = (const float*)d_in[3];
    const float* W2  = (const float*)d_in[4];
    const float* b2  = (const float*)d_in[5];
    const float* fcw = (const float*)d_in[6];
    const float* fcb = (const float*)d_in[7];
    float* out = (float*)d_out;

    const int SMEM = (int)sizeof(Sm);
    cudaFuncSetAttribute(step_kernel<1>,
                         cudaFuncAttributeMaxDynamicSharedMemorySize, SMEM);
    cudaFuncSetAttribute(step_kernel<2>,
                         cudaFuncAttributeMaxDynamicSharedMemorySize, SMEM);

    nbrs_kernel<<<250, 256>>>(adj);
    f0sum_kernel<<<125, 256>>>(X);
    step_kernel<1><<<NN, 1024, SMEM>>>(X, W1, b1);
    step_kernel<2><<<NN, 1024, SMEM>>>(X, W2, b2);
    final_kernel<<<1, 32>>>(fcw, fcb, out);
}

// round 10
// speedup vs baseline: 1.3420x; 1.3420x over previous
#include <cuda_runtime.h>

#define NN 2000
#define PS 516               // floats per (arr,cq) plane (516 mod 32 == 4)
#define ARRF 4128            // floats per contraction array = 8*PS
#define TPAD 268             // padded tile row stride in floats

__device__ int g_nbrs[NN * 16];
__device__ __align__(16) float g_F1[(size_t)NN * 4096];  // 32 MB
__device__ double g_gsum[48];

struct __align__(16) Sm {
    float tile[4][4288];   // A: 4 padded F[j] tiles / s0 staging; B: GEMM partials (16384 fl)
    float Asp[6 * ARRF];   // channel-major swizzled: [arr][cq][swz(pos)] float2
    float4 Wp[768];        // [kp][h] = {We0,We1,Wo0,Wo1}
    float Wvt[1536];       // [cci][h] transposed v-block weights
    float v0[256], v1s[256], v2s[256];
    float v1p[4][256], v2p[4][256], s0dp[4][256];
    float rowt[256], colt[256];
    float red[512];
    float bb[16];
    int nbrs_i[16];
    int nbrs_j[4][16];
    __align__(16) int pi[4][16];
};

__device__ __forceinline__ unsigned sptr(const void* p) {
    return (unsigned)__cvta_generic_to_shared(p);
}
__device__ __forceinline__ float sum2(unsigned long long u) {
    return __uint_as_float((unsigned)u) + __uint_as_float((unsigned)(u >> 32));
}
#define FMA2(acc, x, y) \
    asm("fma.rn.f32x2 %0, %1, %2, %3;" : "=l"(acc) : "l"(x), "l"(y), "l"(acc))
#define LDW2(we, wo, a) \
    asm("ld.shared.v2.b64 {%0,%1}, [%2];" : "=l"(we), "=l"(wo) : "r"(a))
__device__ __forceinline__ int swzf(int x, int y) {
    return x * 16 + (((y ^ x) + 5 * x) & 15);
}
#define GBAR(id) asm volatile("bar.sync %0, 256;" ::"r"(id) : "memory")

// ---------------- kernel 1: neighbor extraction + zero g --------------------
__global__ void nbrs_kernel(const float* __restrict__ adj) {
    if (blockIdx.x == 0 && threadIdx.x < 48) g_gsum[threadIdx.x] = 0.0;
    int w = blockIdx.x * (blockDim.x >> 5) + (threadIdx.x >> 5);
    int lane = threadIdx.x & 31;
    if (w >= NN) return;
    const float* row = adj + (size_t)w * NN;
    int cnt = 0;
    for (int base = 0; base < NN; base += 32) {
        int col = base + lane;
        float v = (col < NN) ? row[col] : 0.f;
        unsigned mask = __ballot_sync(0xffffffffu, v > 0.5f);
        if (v > 0.5f) {
            int pos = cnt + __popc(mask & ((1u << lane) - 1u));
            if (pos < 16) g_nbrs[w * 16 + pos] = col;
        }
        cnt += __popc(mask);
    }
}

// ---------------- kernel 2: F0 channel sums ---------------------------------
__global__ void f0sum_kernel(const float* __restrict__ X) {
    int idx = blockIdx.x * 256 + threadIdx.x;
    float loc[16];
#pragma unroll
    for (int c = 0; c < 16; ++c) loc[c] = 0.f;
    if (idx < NN * 16) {
        int node = g_nbrs[idx];
#pragma unroll
        for (int c = 0; c < 16; ++c) loc[c] = X[node * 16 + c];
    }
#pragma unroll
    for (int c = 0; c < 16; ++c) {
        float v = loc[c];
#pragma unroll
        for (int o = 16; o; o >>= 1) v += __shfl_xor_sync(0xffffffffu, v, o);
        loc[c] = v;
    }
    __shared__ float sh[8][16];
    int wid = threadIdx.x >> 5, lane = threadIdx.x & 31;
    if (lane == 0) {
#pragma unroll
        for (int c = 0; c < 16; ++c) sh[wid][c] = loc[c];
    }
    __syncthreads();
    if (threadIdx.x < 16) {
        float s = 0.f;
#pragma unroll
        for (int w = 0; w < 8; ++w) s += sh[w][threadIdx.x];
        atomicAdd(&g_gsum[threadIdx.x], (double)s);
    }
}

// ---------------- kernel 3/4: one CCN step ----------------------------------
template <int MODE>
__global__ __launch_bounds__(1024, 1) void step_kernel(
    const float* __restrict__ X, const float* __restrict__ Wg,
    const float* __restrict__ bg) {
    extern __shared__ char smraw[];
    Sm* sm = reinterpret_cast<Sm*>(smraw);
    const int i = blockIdx.x;
    const int tid = threadIdx.x;
    const int g = tid >> 8, t = tid & 255;
    const int xa = t >> 4, c = t & 15;

    if (tid < 16) sm->nbrs_i[tid] = g_nbrs[i * 16 + tid];
    if (tid < 768) {
        int kp = tid >> 4, h = tid & 15, arr = kp >> 3, cc = (kp & 7) * 2;
        const float* wb = Wg + h * 288 + arr * 32 + cc;
        sm->Wp[tid] = make_float4(wb[0], wb[1], wb[16], wb[17]);
    }
    for (int idx = tid; idx < 1536; idx += 1024) {
        int cci = idx >> 4, h = idx & 15;
        sm->Wvt[idx] = Wg[h * 288 + 192 + cci];
    }
    if (tid >= 768 && tid < 784) sm->bb[tid - 768] = bg[tid - 768];
    __syncthreads();

    // ---------------- Phase A (group-local barriers) -------------------------
    float s0r[16];
    float s0d = 0.f;
    if (MODE == 2) {
#pragma unroll
        for (int b = 0; b < 16; ++b) s0r[b] = 0.f;
    }
    float v1acc = 0.f, v2acc = 0.f;
    float* ab0 = sm->Asp + (c >> 1) * PS + (c & 1);

    for (int iter = 0; iter < 4; ++iter) {
        const int m = iter * 4 + g;
        const int j = sm->nbrs_i[m];
        if (t < 16) {
            sm->nbrs_j[g][t] = g_nbrs[j * 16 + t];
            __syncwarp(0x0000FFFFu);
            int tgt = sm->nbrs_i[t];
            int p = -1;
#pragma unroll
            for (int q = 0; q < 16; ++q)
                if (sm->nbrs_j[g][q] == tgt) p = q;
            sm->pi[g][t] = p;
        }
        float* tg = sm->tile[g];
        if (MODE == 2) {
            const float4* src = (const float4*)(g_F1 + (size_t)j * 4096);
            float4* dst = (float4*)tg;
#pragma unroll
            for (int r = 0; r < 4; ++r) {
                int f = t + 256 * r;
                dst[(f >> 6) * 67 + (f & 63)] = src[f];
            }
        }
        GBAR(g + 1);

        const int pa = sm->pi[g][xa];
        float* ab = ab0 + swzf(m, xa) * 2;
        if (MODE == 2) {
            int piL[16];
#pragma unroll
            for (int q = 0; q < 16; ++q) piL[q] = sm->pi[g][q];
            const int pm = sm->pi[g][m];
            float rowSum = 0.f, colSum = 0.f, dv0 = 0.f, dv1 = 0.f, dv2 = 0.f;
            if (pa >= 0) {
                const float* tr = tg + pa * TPAD + c;
#pragma unroll
                for (int b = 0; b < 16; ++b) {
                    int pb = piL[b];
                    if (pb >= 0) {
                        float v = tr[pb * 16];
                        s0r[b] += v;
                        rowSum += v;
                    }
                }
                const float* tc = tg + pa * 16 + c;
#pragma unroll
                for (int b = 0; b < 16; ++b) {
                    int pb = piL[b];
                    if (pb >= 0) colSum += tc[pb * TPAD];
                }
                dv2 = tr[pa * 16];
                if (pm >= 0) {
                    dv0 = tg[pm * TPAD + pa * 16 + c];
                    dv1 = tr[pm * 16];
                }
            }
            ab[1 * ARRF] = colSum;  // s1[m][b]
            ab[2 * ARRF] = rowSum;  // s2[m][a]
            ab[3 * ARRF] = dv0;     // d0
            ab[4 * ARRF] = dv1;     // d1
            ab[5 * ARRF] = dv2;     // d2
            v1acc += rowSum;
            v2acc += colSum;
        } else {
            float xv = (pa >= 0) ? X[sm->nbrs_j[g][pa] * 16 + c] : 0.f;
            s0d += xv;
            v1acc += xv;
            v2acc += xv;
            float dvv = (xa == m) ? xv : 0.f;
            ab[1 * ARRF] = xv;
            ab[2 * ARRF] = xv;
            ab[3 * ARRF] = dvv;
            ab[4 * ARRF] = dvv;
            ab[5 * ARRF] = xv;
        }
        GBAR(g + 1);
        if (t < 16) {  // v0[m][c] = sum_a s2[m][a][c]
            const float* s2b = sm->Asp + 2 * ARRF + (t >> 1) * PS + (t & 1);
            float s = 0.f;
#pragma unroll
            for (int a2 = 0; a2 < 16; ++a2) s += s2b[swzf(m, a2) * 2];
            sm->v0[m * 16 + t] = s;
        }
    }

    if (MODE == 2) {
        float* st = &sm->tile[g][xa * 256 + c];
#pragma unroll
        for (int b = 0; b < 16; ++b) st[b * 16] = s0r[b];
    } else {
        sm->s0dp[g][t] = s0d;
    }
    sm->v1p[g][t] = v1acc;
    sm->v2p[g][t] = v2acc;
    __syncthreads();

    // combine s0 -> Asp[0]; v1s/v2s sums
#pragma unroll
    for (int p = 0; p < 4; ++p) {
        int idx = tid + p * 1024;
        int a2 = idx >> 8, b2 = (idx >> 4) & 15, c2 = idx & 15;
        float s;
        if (MODE == 2) {
            s = sm->tile[0][idx] + sm->tile[1][idx] + sm->tile[2][idx] +
                sm->tile[3][idx];
        } else {
            s = (a2 == b2) ? (sm->s0dp[0][a2 * 16 + c2] + sm->s0dp[1][a2 * 16 + c2] +
                              sm->s0dp[2][a2 * 16 + c2] + sm->s0dp[3][a2 * 16 + c2])
                           : 0.f;
        }
        sm->Asp[(c2 >> 1) * PS + swzf(a2, b2) * 2 + (c2 & 1)] = s;
    }
    if (tid < 256) {
        sm->v1s[tid] = sm->v1p[0][tid] + sm->v1p[1][tid] + sm->v1p[2][tid] +
                       sm->v1p[3][tid];
        sm->v2s[tid] = sm->v2p[0][tid] + sm->v2p[1][tid] + sm->v2p[2][tid] +
                       sm->v2p[3][tid];
    }
    __syncthreads();

    // ---------------- Phase B ------------------------------------------------
    // rowt/colt (t<512) then all threads run the GEMM
    if (tid < 512) {
        int half = tid >> 8, al = (tid >> 4) & 15, h = tid & 15;
        float acc = 0.f;
#pragma unroll
        for (int cc = 0; cc < 16; ++cc) {
            float a0 = sm->v0[al * 16 + cc];
            float a1 = sm->v1s[al * 16 + cc];
            float a2v = sm->v2s[al * 16 + cc];
            const float* wv = &sm->Wvt[(half * 16 + cc) * 16 + h];
            acc += a0 * wv[0] + a1 * wv[512] + a2v * wv[1024];
        }
        (half ? sm->colt : sm->rowt)[al * 16 + h] = acc;
    }

    // transpose-pair unrank: 128 units per section cover all 256 positions
    const int sec = tid >> 7, u = tid & 127;
    const int ks = sec >> 1, hs = sec & 1;
    int x1, y1, x2, y2;
    bool diag;
    if (u < 120) {
        int a = 0, rem = u;
        while (rem >= 15 - a) { rem -= 15 - a; ++a; }
        x1 = a; y1 = a + 1 + rem;
        x2 = y1; y2 = x1;
        diag = false;
    } else {
        int d = u - 120;
        x1 = 2 * d; y1 = 2 * d;
        x2 = 2 * d + 1; y2 = 2 * d + 1;
        diag = true;
    }
    const int sw1 = swzf(x1, y1), sw2 = swzf(x2, y2);
    const int pos1 = x1 * 16 + y1, pos2 = x2 * 16 + y2;

    unsigned long long acc1[8], acc2[8];
#pragma unroll
    for (int h = 0; h < 8; ++h) { acc1[h] = 0ull; acc2[h] = 0ull; }
    unsigned wadr = sptr(sm->Wp) + ((ks * 12) * 16 + hs * 8) * 16;

#pragma unroll 4
    for (int uu = 0; uu < 12; ++uu) {
        int kp = ks * 12 + uu;
        const float* pl = sm->Asp + (kp >> 3) * ARRF + (kp & 7) * PS;
        unsigned long long va = *(const unsigned long long*)(pl + sw1 * 2);
        unsigned long long vb = *(const unsigned long long*)(pl + sw2 * 2);
        unsigned long long t1 = diag ? va : vb;
        unsigned long long t2 = diag ? vb : va;
#pragma unroll
        for (int hh = 0; hh < 8; ++hh) {
            unsigned long long we, wo;
            LDW2(we, wo, wadr + uu * 256 + hh * 16);
            FMA2(acc1[hh], va, we);
            FMA2(acc1[hh], t1, wo);
            FMA2(acc2[hh], vb, we);
            FMA2(acc2[hh], t2, wo);
        }
    }
    {
        float* P = &sm->tile[0][0];
        float* p1 = P + (sec * 256 + pos1) * 8;
        float* p2 = P + (sec * 256 + pos2) * 8;
        *(float4*)p1 = make_float4(sum2(acc1[0]), sum2(acc1[1]), sum2(acc1[2]),
                                   sum2(acc1[3]));
        *(float4*)(p1 + 4) = make_float4(sum2(acc1[4]), sum2(acc1[5]),
                                         sum2(acc1[6]), sum2(acc1[7]));
        *(float4*)p2 = make_float4(sum2(acc2[0]), sum2(acc2[1]), sum2(acc2[2]),
                                   sum2(acc2[3]));
        *(float4*)(p2 + 4) = make_float4(sum2(acc2[4]), sum2(acc2[5]),
                                         sum2(acc2[6]), sum2(acc2[7]));
    }
    __syncthreads();

    // final combine
    const int pos = tid >> 2, hq = tid & 3;
    const int alf = pos >> 4, bef = pos & 15;
    const int hsf = hq >> 1, hof = (hq & 1) * 4;
    const float* P = &sm->tile[0][0];
    float4 q0 = *(const float4*)(P + ((0 + hsf) * 256 + pos) * 8 + hof);
    float4 q1 = *(const float4*)(P + ((2 + hsf) * 256 + pos) * 8 + hof);
    float4 q2 = *(const float4*)(P + ((4 + hsf) * 256 + pos) * 8 + hof);
    float4 q3 = *(const float4*)(P + ((6 + hsf) * 256 + pos) * 8 + hof);
    float4 rw = *(const float4*)(&sm->rowt[alf * 16 + hq * 4]);
    float4 cl = *(const float4*)(&sm->colt[bef * 16 + hq * 4]);
    float4 bv = *(const float4*)(&sm->bb[hq * 4]);
    float vals[4];
    vals[0] = fmaxf(q0.x + q1.x + q2.x + q3.x + rw.x + cl.x + bv.x, 0.f);
    vals[1] = fmaxf(q0.y + q1.y + q2.y + q3.y + rw.y + cl.y + bv.y, 0.f);
    vals[2] = fmaxf(q0.z + q1.z + q2.z + q3.z + rw.z + cl.z + bv.z, 0.f);
    vals[3] = fmaxf(q0.w + q1.w + q2.w + q3.w + rw.w + cl.w + bv.w, 0.f);

    if (MODE == 1) {
        float4* out = (float4*)(g_F1 + (size_t)i * 4096 + pos * 16 + hq * 4);
        *out = make_float4(vals[0], vals[1], vals[2], vals[3]);
    }
    const int w = tid >> 5, lane = tid & 31;
#pragma unroll
    for (int k2 = 0; k2 < 4; ++k2) {
        float v = vals[k2];
        v += __shfl_xor_sync(0xffffffffu, v, 4);
        v += __shfl_xor_sync(0xffffffffu, v, 8);
        v += __shfl_xor_sync(0xffffffffu, v, 16);
        vals[k2] = v;
    }
    if (lane < 4) {
#pragma unroll
        for (int k2 = 0; k2 < 4; ++k2) sm->red[w * 16 + lane * 4 + k2] = vals[k2];
    }
    __syncthreads();
    if (tid < 16) {
        float s = 0.f;
#pragma unroll
        for (int w2 = 0; w2 < 32; ++w2) s += sm->red[w2 * 16 + tid];
        atomicAdd(&g_gsum[(MODE == 1 ? 16 : 32) + tid], (double)s);
    }
}

// ---------------- kernel 5: final dot with fc --------------------------------
__global__ void final_kernel(const float* __restrict__ fc_w,
                             const float* __restrict__ fc_b,
                             float* __restrict__ out) {
    if (threadIdx.x == 0) {
        double s = (double)fc_b[0];
#pragma unroll
        for (int c = 0; c < 48; ++c) s += g_gsum[c] * (double)fc_w[c];
        out[0] = (float)s;
    }
}

// ---------------- host entry --------------------------------------------------
extern "C" void kernel_launch(void* const* d_in, const int* in_sizes, int n_in,
                              void* d_out, int out_size) {
    const float* X   = (const float*)d_in[0];
    const float* adj = (const float*)d_in[1];
    const float* W1  = (const float*)d_in[2];
    const float* b1  = (const float*)d_in[3];
    const float* W2  = (const float*)d_in[4];
    const float* b2  = (const float*)d_in[5];
    const float* fcw = (const float*)d_in[6];
    const float* fcb = (const float*)d_in[7];
    float* out = (float*)d_out;

    const int SMEM = (int)sizeof(Sm);
    cudaFuncSetAttribute(step_kernel<1>,
                         cudaFuncAttributeMaxDynamicSharedMemorySize, SMEM);
    cudaFuncSetAttribute(step_kernel<2>,
                         cudaFuncAttributeMaxDynamicSharedMemorySize, SMEM);

    nbrs_kernel<<<250, 256>>>(adj);
    f0sum_kernel<<<125, 256>>>(X);
    step_kernel<1><<<NN, 1024, SMEM>>>(X, W1, b1);
    step_kernel<2><<<NN, 1024, SMEM>>>(X, W2, b2);
    final_kernel<<<1, 32>>>(fcw, fcb, out);
}

// round 12
// speedup vs baseline: 1.5929x; 1.1870x over previous
#include <cuda_runtime.h>

#define NN 2000
#define PS 516               // floats per (arr,cq) plane (516 mod 32 == 4)
#define ARRF 4128            // floats per contraction array = 8*PS
#define TPAD 268             // padded tile row stride (floats)
#define SSTR 264             // s0 staging row stride (floats)

__device__ int g_nbrs[NN * 16];
__device__ __align__(16) float g_F1[(size_t)NN * 4096];  // 32 MB
__device__ double g_gsum[48];

struct __align__(16) Sm {
    float tile[4][4288];   // A: padded F[j] tiles / s0 staging; B: GEMM partials
    float Asp[6 * ARRF];   // channel-pair-major swizzled contraction arrays
    float4 Wp[768];        // [kp][h] = {We0,We1,Wo0,Wo1}
    float Wvt[1536];       // [cci][h] transposed v-block weights
    float v0[256], v1s[256], v2s[256];
    float v1p[4][256], v2p[4][256], s0dp[4][256];
    float rowt[256], colt[256];
    float diagS0[256], diagD[256], wd1[256], wd2[256], corr[256];
    float red[512];
    float bb[16];
    int nbrs_i[16];
    int nbrs_j[4][16];
    __align__(16) int pi[4][16];
};

__device__ __forceinline__ unsigned sptr(const void* p) {
    return (unsigned)__cvta_generic_to_shared(p);
}
__device__ __forceinline__ float sum2(unsigned long long u) {
    return __uint_as_float((unsigned)u) + __uint_as_float((unsigned)(u >> 32));
}
#define FMA2(acc, x, y) \
    asm("fma.rn.f32x2 %0, %1, %2, %3;" : "=l"(acc) : "l"(x), "l"(y), "l"(acc))
#define LDW2(we, wo, a) \
    asm("ld.shared.v2.b64 {%0,%1}, [%2];" : "=l"(we), "=l"(wo) : "r"(a))
__device__ __forceinline__ int swzf(int x, int y) {
    return x * 16 + (((y ^ x) + 5 * x) & 15);
}
#define GBAR(id) asm volatile("bar.sync %0, 256;" ::"r"(id) : "memory")

// ---------------- kernel 1: neighbor extraction + zero g --------------------
__global__ void nbrs_kernel(const float* __restrict__ adj) {
    if (blockIdx.x == 0 && threadIdx.x < 48) g_gsum[threadIdx.x] = 0.0;
    int w = blockIdx.x * (blockDim.x >> 5) + (threadIdx.x >> 5);
    int lane = threadIdx.x & 31;
    if (w >= NN) return;
    const float* row = adj + (size_t)w * NN;
    int cnt = 0;
    for (int base = 0; base < NN; base += 32) {
        int col = base + lane;
        float v = (col < NN) ? row[col] : 0.f;
        unsigned mask = __ballot_sync(0xffffffffu, v > 0.5f);
        if (v > 0.5f) {
            int pos = cnt + __popc(mask & ((1u << lane) - 1u));
            if (pos < 16) g_nbrs[w * 16 + pos] = col;
        }
        cnt += __popc(mask);
    }
}

// ---------------- kernel 2: F0 channel sums ---------------------------------
__global__ void f0sum_kernel(const float* __restrict__ X) {
    int idx = blockIdx.x * 256 + threadIdx.x;
    float loc[16];
#pragma unroll
    for (int c = 0; c < 16; ++c) loc[c] = 0.f;
    if (idx < NN * 16) {
        int node = g_nbrs[idx];
#pragma unroll
        for (int c = 0; c < 16; ++c) loc[c] = X[node * 16 + c];
    }
#pragma unroll
    for (int c = 0; c < 16; ++c) {
        float v = loc[c];
#pragma unroll
        for (int o = 16; o; o >>= 1) v += __shfl_xor_sync(0xffffffffu, v, o);
        loc[c] = v;
    }
    __shared__ float sh[8][16];
    int wid = threadIdx.x >> 5, lane = threadIdx.x & 31;
    if (lane == 0) {
#pragma unroll
        for (int c = 0; c < 16; ++c) sh[wid][c] = loc[c];
    }
    __syncthreads();
    if (threadIdx.x < 16) {
        float s = 0.f;
#pragma unroll
        for (int w = 0; w < 8; ++w) s += sh[w][threadIdx.x];
        atomicAdd(&g_gsum[threadIdx.x], (double)s);
    }
}

// ---------------- kernel 3/4: one CCN step ----------------------------------
template <int MODE>
__global__ __launch_bounds__(1024, 1) void step_kernel(
    const float* __restrict__ X, const float* __restrict__ Wg,
    const float* __restrict__ bg) {
    extern __shared__ char smraw[];
    Sm* sm = reinterpret_cast<Sm*>(smraw);
    const int i = blockIdx.x;
    const int tid = threadIdx.x;
    const int g = tid >> 8, t = tid & 255;

    if (tid < 16) sm->nbrs_i[tid] = g_nbrs[i * 16 + tid];
    if (MODE == 2) {
        if (tid < 768) {
            int kp = tid >> 4, h = tid & 15, arr = kp >> 3, cc = (kp & 7) * 2;
            const float* wb = Wg + h * 288 + arr * 32 + cc;
            sm->Wp[tid] = make_float4(wb[0], wb[1], wb[16], wb[17]);
        }
    } else {
        if (tid < 128) {  // combined dense weights: blocks {2,4,10}/{3,5,11}
            int kp = tid >> 4, h = tid & 15, cc = kp * 2;
            const float* wb = Wg + h * 288;
            sm->Wp[tid] = make_float4(
                wb[32 + cc] + wb[64 + cc] + wb[160 + cc],
                wb[33 + cc] + wb[65 + cc] + wb[161 + cc],
                wb[48 + cc] + wb[80 + cc] + wb[176 + cc],
                wb[49 + cc] + wb[81 + cc] + wb[177 + cc]);
        } else if (tid < 384) {  // diag-correction weights
            int ii = tid - 128, h = ii >> 4, c = ii & 15;
            const float* wb = Wg + h * 288;
            sm->wd1[ii] = wb[c] + wb[16 + c];
            sm->wd2[ii] = wb[96 + c] + wb[112 + c] + wb[128 + c] + wb[144 + c];
        }
    }
    for (int idx = tid; idx < 1536; idx += 1024) {
        int cci = idx >> 4, h = idx & 15;
        sm->Wvt[idx] = Wg[h * 288 + 192 + cci];
    }
    if (tid >= 768 && tid < 784) sm->bb[tid - 768] = bg[tid - 768];
    __syncthreads();

    // ---------------- Phase A ------------------------------------------------
    if (MODE == 2) {
        const int a = t >> 4, c2 = (t & 15) >> 1, hb = t & 1;
        float2 s0r2[8];
#pragma unroll
        for (int k = 0; k < 8; ++k) s0r2[k] = make_float2(0.f, 0.f);
        float2 v1a = make_float2(0.f, 0.f), v2a = make_float2(0.f, 0.f);

        for (int iter = 0; iter < 4; ++iter) {
            const int m = iter * 4 + g;
            const int j = sm->nbrs_i[m];
            if (t < 16) {
                sm->nbrs_j[g][t] = g_nbrs[j * 16 + t];
                __syncwarp(0x0000FFFFu);
                int tgt = sm->nbrs_i[t];
                int p = -1;
#pragma unroll
                for (int q = 0; q < 16; ++q)
                    if (sm->nbrs_j[g][q] == tgt) p = q;
                sm->pi[g][t] = p;
            }
            float* tg = sm->tile[g];
            {
                const float4* src = (const float4*)(g_F1 + (size_t)j * 4096);
                float4* dst = (float4*)tg;
#pragma unroll
                for (int r = 0; r < 4; ++r) {
                    int f = t + 256 * r;
                    dst[(f >> 6) * 67 + (f & 63)] = src[f];
                }
            }
            GBAR(g + 1);

            const int pa = sm->pi[g][a];
            int4 qA = *(const int4*)&sm->pi[g][hb * 8];
            int4 qB = *(const int4*)&sm->pi[g][hb * 8 + 4];
            const int pbs[8] = {qA.x, qA.y, qA.z, qA.w, qB.x, qB.y, qB.z, qB.w};
            const float* tr = tg + pa * TPAD + 2 * c2;
            float2 rs = make_float2(0.f, 0.f);
            float2 dv1 = make_float2(0.f, 0.f), dv2 = make_float2(0.f, 0.f);
            if (pa >= 0) {
#pragma unroll
                for (int k = 0; k < 8; ++k) {
                    int b = hb * 8 + k, pb = pbs[k];
                    if (pb >= 0) {
                        float2 v = *(const float2*)(tr + pb * 16);
                        s0r2[k].x += v.x; s0r2[k].y += v.y;
                        rs.x += v.x; rs.y += v.y;
                        if (b == a) dv2 = v;
                        if (b == m) dv1 = v;
                    }
                }
            }
            float* A1 = sm->Asp + c2 * PS;
            if (hb == (a >> 3)) *(float2*)(A1 + 5 * ARRF + swzf(m, a) * 2) = dv2;
            if (hb == (m >> 3)) *(float2*)(A1 + 4 * ARRF + swzf(m, a) * 2) = dv1;
            rs.x += __shfl_xor_sync(0xffffffffu, rs.x, 1);
            rs.y += __shfl_xor_sync(0xffffffffu, rs.y, 1);
            if (hb == 0) {
                *(float2*)(A1 + 2 * ARRF + swzf(m, a) * 2) = rs;
                v1a.x += rs.x; v1a.y += rs.y;
            }
            if (a == m) {  // d0[m][b] = T[m][b]
#pragma unroll
                for (int k = 0; k < 8; ++k) {
                    int b = hb * 8 + k, pb = pbs[k];
                    float2 v = make_float2(0.f, 0.f);
                    if (pa >= 0 && pb >= 0) v = *(const float2*)(tr + pb * 16);
                    *(float2*)(A1 + 3 * ARRF + swzf(m, b) * 2) = v;
                }
            }
            // col pass: this thread plays b = a
            float2 cs = make_float2(0.f, 0.f);
            const float* tc = tg + pa * 16 + 2 * c2;
            if (pa >= 0) {
#pragma unroll
                for (int k = 0; k < 8; ++k) {
                    int pa2 = pbs[k];
                    if (pa2 >= 0) {
                        float2 v = *(const float2*)(tc + pa2 * TPAD);
                        cs.x += v.x; cs.y += v.y;
                    }
                }
            }
            cs.x += __shfl_xor_sync(0xffffffffu, cs.x, 1);
            cs.y += __shfl_xor_sync(0xffffffffu, cs.y, 1);
            if (hb == 0) {
                *(float2*)(A1 + 1 * ARRF + swzf(m, a) * 2) = cs;
                v2a.x += cs.x; v2a.y += cs.y;
            }
            GBAR(g + 1);
            if (t < 16) {  // v0[m][c] = sum_a s2[m][a][c]
                const float* s2b = sm->Asp + 2 * ARRF + (t >> 1) * PS + (t & 1);
                float s = 0.f;
#pragma unroll
                for (int a2 = 0; a2 < 16; ++a2) s += s2b[swzf(m, a2) * 2];
                sm->v0[m * 16 + t] = s;
            }
        }
        // stage s0 partials + v partials
        {
            float* stg = sm->tile[g];
#pragma unroll
            for (int k = 0; k < 8; ++k) {
                int b = hb * 8 + k;
                *(float2*)(stg + a * SSTR + b * 16 + 2 * c2) = s0r2[k];
            }
            if (hb == 0) {
                *(float2*)(&sm->v1p[g][a * 16 + 2 * c2]) = v1a;
                *(float2*)(&sm->v2p[g][a * 16 + 2 * c2]) = v2a;
            }
        }
        __syncthreads();
#pragma unroll
        for (int p = 0; p < 4; ++p) {  // combine s0 -> Asp[0]
            int idx = tid + p * 1024;
            int a2 = idx >> 8, b2 = (idx >> 4) & 15, cx = idx & 15;
            int off = a2 * SSTR + b2 * 16 + cx;
            float s = sm->tile[0][off] + sm->tile[1][off] + sm->tile[2][off] +
                      sm->tile[3][off];
            sm->Asp[(cx >> 1) * PS + swzf(a2, b2) * 2 + (cx & 1)] = s;
        }
        if (tid < 256) {
            sm->v1s[tid] = sm->v1p[0][tid] + sm->v1p[1][tid] + sm->v1p[2][tid] +
                           sm->v1p[3][tid];
            sm->v2s[tid] = sm->v2p[0][tid] + sm->v2p[1][tid] + sm->v2p[2][tid] +
                           sm->v2p[3][tid];
        }
        __syncthreads();
    } else {
        // MODE 1: diagonal T; single dense array (=s1=s2=d2) + diag vectors
        const int xa = t >> 4, c = t & 15;
        float s0d = 0.f, v1acc = 0.f, v2acc = 0.f;
        for (int iter = 0; iter < 4; ++iter) {
            const int m = iter * 4 + g;
            const int j = sm->nbrs_i[m];
            if (t < 16) {
                sm->nbrs_j[g][t] = g_nbrs[j * 16 + t];
                __syncwarp(0x0000FFFFu);
                int tgt = sm->nbrs_i[t];
                int p = -1;
#pragma unroll
                for (int q = 0; q < 16; ++q)
                    if (sm->nbrs_j[g][q] == tgt) p = q;
                sm->pi[g][t] = p;
            }
            GBAR(g + 1);
            const int pa = sm->pi[g][xa];
            float xv = (pa >= 0) ? X[sm->nbrs_j[g][pa] * 16 + c] : 0.f;
            s0d += xv; v1acc += xv; v2acc += xv;
            sm->Asp[(c >> 1) * PS + swzf(m, xa) * 2 + (c & 1)] = xv;
            if (xa == m) sm->diagD[xa * 16 + c] = xv;
            GBAR(g + 1);
            if (t < 16) {
                const float* s2b = sm->Asp + (t >> 1) * PS + (t & 1);
                float s = 0.f;
#pragma unroll
                for (int a2 = 0; a2 < 16; ++a2) s += s2b[swzf(m, a2) * 2];
                sm->v0[m * 16 + t] = s;
            }
        }
        sm->s0dp[g][t] = s0d;
        sm->v1p[g][t] = v1acc;
        sm->v2p[g][t] = v2acc;
        __syncthreads();
        if (tid < 256) {
            sm->diagS0[tid] = sm->s0dp[0][tid] + sm->s0dp[1][tid] +
                              sm->s0dp[2][tid] + sm->s0dp[3][tid];
            sm->v1s[tid] = sm->v1p[0][tid] + sm->v1p[1][tid] + sm->v1p[2][tid] +
                           sm->v1p[3][tid];
            sm->v2s[tid] = sm->v2p[0][tid] + sm->v2p[1][tid] + sm->v2p[2][tid] +
                           sm->v2p[3][tid];
        }
        __syncthreads();
    }

    // ---------------- Phase B ------------------------------------------------
    if (tid < 512) {  // rowt / colt from v-blocks
        int half = tid >> 8, al = (tid >> 4) & 15, h = tid & 15;
        float acc = 0.f;
#pragma unroll
        for (int cc = 0; cc < 16; ++cc) {
            float a0 = sm->v0[al * 16 + cc];
            float a1 = sm->v1s[al * 16 + cc];
            float a2v = sm->v2s[al * 16 + cc];
            const float* wv = &sm->Wvt[(half * 16 + cc) * 16 + h];
            acc += a0 * wv[0] + a1 * wv[512] + a2v * wv[1024];
        }
        (half ? sm->colt : sm->rowt)[al * 16 + h] = acc;
    } else if (MODE == 1 && tid < 768) {  // diag corrections
        int x = (tid >> 4) & 15, h = tid & 15;
        float acc = 0.f;
#pragma unroll
        for (int cc = 0; cc < 16; ++cc)
            acc += sm->diagS0[x * 16 + cc] * sm->wd1[h * 16 + cc] +
                   sm->diagD[x * 16 + cc] * sm->wd2[h * 16 + cc];
        sm->corr[x * 16 + h] = acc;
    }

    // dense GEMM: transpose-pair unrank, 8 sections (4 ks x 2 hs)
    const int UU = (MODE == 1) ? 2 : 12;
    const int sec = tid >> 7, u = tid & 127;
    const int ks = sec >> 1, hs = sec & 1;
    int x1, y1, x2, y2;
    bool diag;
    if (u < 120) {
        int a = 0, rem = u;
        while (rem >= 15 - a) { rem -= 15 - a; ++a; }
        x1 = a; y1 = a + 1 + rem;
        x2 = y1; y2 = x1;
        diag = false;
    } else {
        int d = u - 120;
        x1 = 2 * d; y1 = 2 * d;
        x2 = 2 * d + 1; y2 = 2 * d + 1;
        diag = true;
    }
    const int sw1 = swzf(x1, y1), sw2 = swzf(x2, y2);
    const int pos1 = x1 * 16 + y1, pos2 = x2 * 16 + y2;

    unsigned long long acc1[8], acc2[8];
#pragma unroll
    for (int h = 0; h < 8; ++h) { acc1[h] = 0ull; acc2[h] = 0ull; }
    unsigned wadr = sptr(sm->Wp) + ((ks * UU) * 16 + hs * 8) * 16;

#pragma unroll
    for (int uu = 0; uu < UU; ++uu) {
        int kp = ks * UU + uu;
        const float* pl = sm->Asp + (kp >> 3) * ARRF + (kp & 7) * PS;
        unsigned long long va = *(const unsigned long long*)(pl + sw1 * 2);
        unsigned long long vb = *(const unsigned long long*)(pl + sw2 * 2);
        unsigned long long t1 = diag ? va : vb;
        unsigned long long t2 = diag ? vb : va;
#pragma unroll
        for (int hh = 0; hh < 8; ++hh) {
            unsigned long long we, wo;
            LDW2(we, wo, wadr + uu * 256 + hh * 16);
            FMA2(acc1[hh], va, we);
            FMA2(acc1[hh], t1, wo);
            FMA2(acc2[hh], vb, we);
            FMA2(acc2[hh], t2, wo);
        }
    }
    {
        float* P = &sm->tile[0][0];
        float* p1 = P + (sec * 256 + pos1) * 8;
        float* p2 = P + (sec * 256 + pos2) * 8;
        *(float4*)p1 = make_float4(sum2(acc1[0]), sum2(acc1[1]), sum2(acc1[2]),
                                   sum2(acc1[3]));
        *(float4*)(p1 + 4) = make_float4(sum2(acc1[4]), sum2(acc1[5]),
                                         sum2(acc1[6]), sum2(acc1[7]));
        *(float4*)p2 = make_float4(sum2(acc2[0]), sum2(acc2[1]), sum2(acc2[2]),
                                   sum2(acc2[3]));
        *(float4*)(p2 + 4) = make_float4(sum2(acc2[4]), sum2(acc2[5]),
                                         sum2(acc2[6]), sum2(acc2[7]));
    }
    __syncthreads();

    // final combine
    const int pos = tid >> 2, hq = tid & 3;
    const int alf = pos >> 4, bef = pos & 15;
    const int hsf = hq >> 1, hof = (hq & 1) * 4;
    const float* P = &sm->tile[0][0];
    float4 q0 = *(const float4*)(P + ((0 + hsf) * 256 + pos) * 8 + hof);
    float4 q1 = *(const float4*)(P + ((2 + hsf) * 256 + pos) * 8 + hof);
    float4 q2 = *(const float4*)(P + ((4 + hsf) * 256 + pos) * 8 + hof);
    float4 q3 = *(const float4*)(P + ((6 + hsf) * 256 + pos) * 8 + hof);
    float4 rw = *(const float4*)(&sm->rowt[alf * 16 + hq * 4]);
    float4 cl = *(const float4*)(&sm->colt[bef * 16 + hq * 4]);
    float4 bv = *(const float4*)(&sm->bb[hq * 4]);
    float vals[4];
    vals[0] = q0.x + q1.x + q2.x + q3.x + rw.x + cl.x + bv.x;
    vals[1] = q0.y + q1.y + q2.y + q3.y + rw.y + cl.y + bv.y;
    vals[2] = q0.z + q1.z + q2.z + q3.z + rw.z + cl.z + bv.z;
    vals[3] = q0.w + q1.w + q2.w + q3.w + rw.w + cl.w + bv.w;
    if (MODE == 1 && alf == bef) {
        float4 cr = *(const float4*)(&sm->corr[alf * 16 + hq * 4]);
        vals[0] += cr.x; vals[1] += cr.y; vals[2] += cr.z; vals[3] += cr.w;
    }
    vals[0] = fmaxf(vals[0], 0.f);
    vals[1] = fmaxf(vals[1], 0.f);
    vals[2] = fmaxf(vals[2], 0.f);
    vals[3] = fmaxf(vals[3], 0.f);

    if (MODE == 1) {
        float4* out = (float4*)(g_F1 + (size_t)i * 4096 + pos * 16 + hq * 4);
        *out = make_float4(vals[0], vals[1], vals[2], vals[3]);
    }
    const int w = tid >> 5, lane = tid & 31;
#pragma unroll
    for (int k2 = 0; k2 < 4; ++k2) {
        float v = vals[k2];
        v += __shfl_xor_sync(0xffffffffu, v, 4);
        v += __shfl_xor_sync(0xffffffffu, v, 8);
        v += __shfl_xor_sync(0xffffffffu, v, 16);
        vals[k2] = v;
    }
    if (lane < 4) {
#pragma unroll
        for (int k2 = 0; k2 < 4; ++k2) sm->red[w * 16 + lane * 4 + k2] = vals[k2];
    }
    __syncthreads();
    if (tid < 16) {
        float s = 0.f;
#pragma unroll
        for (int w2 = 0; w2 < 32; ++w2) s += sm->red[w2 * 16 + tid];
        atomicAdd(&g_gsum[(MODE == 1 ? 16 : 32) + tid], (double)s);
    }
}

// ---------------- kernel 5: final dot with fc --------------------------------
__global__ void final_kernel(const float* __restrict__ fc_w,
                             const float* __restrict__ fc_b,
                             float* __restrict__ out) {
    if (threadIdx.x == 0) {
        double s = (double)fc_b[0];
#pragma unroll
        for (int c = 0; c < 48; ++c) s += g_gsum[c] * (double)fc_w[c];
        out[0] = (float)s;
    }
}

// ---------------- host entry --------------------------------------------------
extern "C" void kernel_launch(void* const* d_in, const int* in_sizes, int n_in,
                              void* d_out, int out_size) {
    const float* X   = (const float*)d_in[0];
    const float* adj = (const float*)d_in[1];
    const float* W1  = (const float*)d_in[2];
    const float* b1  = (const float*)d_in[3];
    const float* W2  = (const float*)d_in[4];
    const float* b2  = (const float*)d_in[5];
    const float* fcw = (const float*)d_in[6];
    const float* fcb = (const float*)d_in[7];
    float* out = (float*)d_out;

    const int SMEM = (int)sizeof(Sm);
    cudaFuncSetAttribute(step_kernel<1>,
                         cudaFuncAttributeMaxDynamicSharedMemorySize, SMEM);
    cudaFuncSetAttribute(step_kernel<2>,
                         cudaFuncAttributeMaxDynamicSharedMemorySize, SMEM);

    nbrs_kernel<<<250, 256>>>(adj);
    f0sum_kernel<<<125, 256>>>(X);
    step_kernel<1><<<NN, 1024, SMEM>>>(X, W1, b1);
    step_kernel<2><<<NN, 1024, SMEM>>>(X, W2, b2);
    final_kernel<<<1, 32>>>(fcw, fcb, out);
}

// round 14
// speedup vs baseline: 2.0194x; 1.2677x over previous
#include <cuda_runtime.h>

#define NN 2000
#define PS 516               // floats per (arr,cq) plane (516 mod 32 == 4)
#define ARRF 4128            // floats per contraction array = 8*PS

__device__ int g_nbrs[NN * 16];
__device__ __align__(16) float g_F1[(size_t)NN * 4096];  // 32 MB
__device__ double g_gsum[48];

// ---------------- shared layouts ---------------------------------------------
struct __align__(16) Sm2 {
    float Asp[6 * ARRF];   // swizzled contraction arrays
    float P[16896];        // s0 staging (4 x 4224) then GEMM partials (16384)
    float4 Wp[768];        // [kp][h] = {We0,We1,Wo0,Wo1}
    float Wvt[1536];       // [cci][h] transposed v-block weights
    float v0[256], v1s[256], v2s[256];
    float v1p[4][256], v2p[4][256];
    float rowt[256], colt[256];
    float red[512];
    float bb[16];
    int nbrs_i[16];
    int nbrs_j[16][16];
    __align__(16) int pi[16][16];
};

struct __align__(16) Sm1 {
    float Asp[ARRF];       // dense array (= s1 = s2 = d2), swizzled
    float4 Wp[128];        // combined dense weights [kp][h]
    float Wvt[1536];
    float wd1[256], wd2[256];
    float v0[256], v1s[256];
    float rowt[256], colt[256], corr[256];
    float red[8][8];
    float bb[16];
    int nbrs_i[16];
    int nbrs_j[16][16];
    __align__(16) int pi[16][16];
};

__device__ __forceinline__ unsigned sptr(const void* p) {
    return (unsigned)__cvta_generic_to_shared(p);
}
__device__ __forceinline__ float sum2(unsigned long long u) {
    return __uint_as_float((unsigned)u) + __uint_as_float((unsigned)(u >> 32));
}
#define FMA2(acc, x, y) \
    asm("fma.rn.f32x2 %0, %1, %2, %3;" : "=l"(acc) : "l"(x), "l"(y), "l"(acc))
#define LDW2(we, wo, a) \
    asm("ld.shared.v2.b64 {%0,%1}, [%2];" : "=l"(we), "=l"(wo) : "r"(a))
__device__ __forceinline__ int swzf(int x, int y) {
    return x * 16 + (((y ^ x) + 5 * x) & 15);
}
__device__ __forceinline__ void unrank(int u, int& x1, int& y1, int& x2,
                                       int& y2, bool& diag) {
    if (u < 120) {
        int a = 0, rem = u;
        while (rem >= 15 - a) { rem -= 15 - a; ++a; }
        x1 = a; y1 = a + 1 + rem; x2 = y1; y2 = x1; diag = false;
    } else {
        int d = u - 120;
        x1 = 2 * d; y1 = 2 * d; x2 = 2 * d + 1; y2 = 2 * d + 1; diag = true;
    }
}

// ---------------- kernel 1: neighbor extraction + zero g --------------------
__global__ void nbrs_kernel(const float* __restrict__ adj) {
    if (blockIdx.x == 0 && threadIdx.x < 48) g_gsum[threadIdx.x] = 0.0;
    int w = blockIdx.x * (blockDim.x >> 5) + (threadIdx.x >> 5);
    int lane = threadIdx.x & 31;
    if (w >= NN) return;
    const float* row = adj + (size_t)w * NN;
    int cnt = 0;
    for (int base = 0; base < NN; base += 32) {
        int col = base + lane;
        float v = (col < NN) ? row[col] : 0.f;
        unsigned mask = __ballot_sync(0xffffffffu, v > 0.5f);
        if (v > 0.5f) {
            int pos = cnt + __popc(mask & ((1u << lane) - 1u));
            if (pos < 16) g_nbrs[w * 16 + pos] = col;
        }
        cnt += __popc(mask);
    }
}

// ---------------- kernel 2: F0 channel sums ---------------------------------
__global__ void f0sum_kernel(const float* __restrict__ X) {
    int idx = blockIdx.x * 256 + threadIdx.x;
    float loc[16];
#pragma unroll
    for (int c = 0; c < 16; ++c) loc[c] = 0.f;
    if (idx < NN * 16) {
        int node = g_nbrs[idx];
#pragma unroll
        for (int c = 0; c < 16; ++c) loc[c] = X[node * 16 + c];
    }
#pragma unroll
    for (int c = 0; c < 16; ++c) {
        float v = loc[c];
#pragma unroll
        for (int o = 16; o; o >>= 1) v += __shfl_xor_sync(0xffffffffu, v, o);
        loc[c] = v;
    }
    __shared__ float sh[8][16];
    int wid = threadIdx.x >> 5, lane = threadIdx.x & 31;
    if (lane == 0) {
#pragma unroll
        for (int c = 0; c < 16; ++c) sh[wid][c] = loc[c];
    }
    __syncthreads();
    if (threadIdx.x < 16) {
        float s = 0.f;
#pragma unroll
        for (int w = 0; w < 8; ++w) s += sh[w][threadIdx.x];
        atomicAdd(&g_gsum[threadIdx.x], (double)s);
    }
}

// ---------------- kernel 3: layer-1 step (diagonal F0 specialization) -------
__global__ __launch_bounds__(256, 4) void step1_kernel(
    const float* __restrict__ X, const float* __restrict__ Wg,
    const float* __restrict__ bg) {
    __shared__ Sm1 sm;
    const int i = blockIdx.x;
    const int tid = threadIdx.x;

    if (tid < 16) {
        sm.nbrs_i[tid] = g_nbrs[i * 16 + tid];
        sm.bb[tid] = bg[tid];
    }
    if (tid < 128) {  // combined dense weights: even {2,4,10}, odd {3,5,11}
        int kp = tid >> 4, h = tid & 15, cc = kp * 2;
        const float* wb = Wg + h * 288;
        sm.Wp[tid] = make_float4(
            wb[32 + cc] + wb[64 + cc] + wb[160 + cc],
            wb[33 + cc] + wb[65 + cc] + wb[161 + cc],
            wb[48 + cc] + wb[80 + cc] + wb[176 + cc],
            wb[49 + cc] + wb[81 + cc] + wb[177 + cc]);
    }
    {  // diag-correction weights (all 256 threads)
        int h = tid >> 4, c = tid & 15;
        const float* wb = Wg + h * 288;
        sm.wd1[tid] = wb[c] + wb[16 + c];
        sm.wd2[tid] = wb[96 + c] + wb[112 + c] + wb[128 + c] + wb[144 + c];
    }
#pragma unroll
    for (int idx = tid; idx < 1536; idx += 256) {
        int cci = idx >> 4, h = idx & 15;
        sm.Wvt[idx] = Wg[h * 288 + 192 + cci];
    }
    __syncthreads();
    {
        int m = tid >> 4, aa = tid & 15;
        sm.nbrs_j[m][aa] = g_nbrs[sm.nbrs_i[m] * 16 + aa];
    }
    __syncthreads();
    {
        int m = tid >> 4, aa = tid & 15;
        int tgt = sm.nbrs_i[aa];
        int p = -1;
#pragma unroll
        for (int q = 0; q < 16; ++q)
            if (sm.nbrs_j[m][q] == tgt) p = q;
        sm.pi[m][aa] = p;
    }
    __syncthreads();

    // phase A: dense[m][a][c] = xv; v1 = col sums (per-thread accumulator)
    {
        const int xa = tid >> 4, c = tid & 15;
        float v1acc = 0.f;
        float* asw = sm.Asp + (c >> 1) * PS + (c & 1);
#pragma unroll
        for (int m = 0; m < 16; ++m) {
            int pa = sm.pi[m][xa];
            float xv = 0.f;
            if (pa >= 0) xv = X[sm.nbrs_j[m][pa] * 16 + c];
            v1acc += xv;
            asw[swzf(m, xa) * 2] = xv;
        }
        sm.v1s[xa * 16 + c] = v1acc;
    }
    __syncthreads();
    {  // v0[m][c] = row sums
        int m = tid >> 4, cx = tid & 15;
        const float* s2b = sm.Asp + (cx >> 1) * PS + (cx & 1);
        float s = 0.f;
#pragma unroll
        for (int a2 = 0; a2 < 16; ++a2) s += s2b[swzf(m, a2) * 2];
        sm.v0[m * 16 + cx] = s;
    }
    __syncthreads();
    {  // rowt / colt / corr, thread = (x, h)
        int x = tid >> 4, h = tid & 15;
        float r = 0.f, ct = 0.f, co = 0.f;
#pragma unroll
        for (int cc = 0; cc < 16; ++cc) {
            float a0 = sm.v0[x * 16 + cc];
            float a1 = sm.v1s[x * 16 + cc];
            r += a0 * sm.Wvt[cc * 16 + h] +
                 a1 * (sm.Wvt[(32 + cc) * 16 + h] + sm.Wvt[(64 + cc) * 16 + h]);
            ct += a0 * sm.Wvt[(16 + cc) * 16 + h] +
                  a1 * (sm.Wvt[(48 + cc) * 16 + h] + sm.Wvt[(80 + cc) * 16 + h]);
            float dd = sm.Asp[(cc >> 1) * PS + swzf(x, x) * 2 + (cc & 1)];
            co += a1 * sm.wd1[h * 16 + cc] + dd * sm.wd2[h * 16 + cc];
        }
        sm.rowt[x * 16 + h] = r;
        sm.colt[x * 16 + h] = ct;
        sm.corr[x * 16 + h] = co;
    }
    __syncthreads();

    // dense GEMM: 2 h-halves x 128 transpose-pair units
    const int hs = tid >> 7, u = tid & 127;
    int x1, y1, x2, y2;
    bool diag;
    unrank(u, x1, y1, x2, y2, diag);
    const int sw1 = swzf(x1, y1), sw2 = swzf(x2, y2);
    unsigned long long acc1[8], acc2[8];
#pragma unroll
    for (int h = 0; h < 8; ++h) { acc1[h] = 0ull; acc2[h] = 0ull; }
    unsigned wadr = sptr(sm.Wp) + hs * 128;
#pragma unroll
    for (int kp = 0; kp < 8; ++kp) {
        const float* pl = sm.Asp + kp * PS;
        unsigned long long va = *(const unsigned long long*)(pl + sw1 * 2);
        unsigned long long vb = *(const unsigned long long*)(pl + sw2 * 2);
        unsigned long long t1 = diag ? va : vb;
        unsigned long long t2 = diag ? vb : va;
#pragma unroll
        for (int hh = 0; hh < 8; ++hh) {
            unsigned long long we, wo;
            LDW2(we, wo, wadr + kp * 256 + hh * 16);
            FMA2(acc1[hh], va, we);
            FMA2(acc1[hh], t1, wo);
            FMA2(acc2[hh], vb, we);
            FMA2(acc2[hh], t2, wo);
        }
    }
    // finalize: bias + row/col terms (+ diag corr), ReLU, write F1, g-accum
    float g8[8];
    {
        float v1v[8], v2v[8];
#pragma unroll
        for (int hh = 0; hh < 8; ++hh) {
            int h = hs * 8 + hh;
            float v = sum2(acc1[hh]) + sm.rowt[x1 * 16 + h] +
                      sm.colt[y1 * 16 + h] + sm.bb[h];
            if (diag) v += sm.corr[x1 * 16 + h];
            v1v[hh] = fmaxf(v, 0.f);
            float w2 = sum2(acc2[hh]) + sm.rowt[x2 * 16 + h] +
                       sm.colt[y2 * 16 + h] + sm.bb[h];
            if (diag) w2 += sm.corr[x2 * 16 + h];
            v2v[hh] = fmaxf(w2, 0.f);
            g8[hh] = v1v[hh] + v2v[hh];
        }
        float4* o1 = (float4*)(g_F1 + (size_t)i * 4096 + (x1 * 16 + y1) * 16 +
                               hs * 8);
        o1[0] = make_float4(v1v[0], v1v[1], v1v[2], v1v[3]);
        o1[1] = make_float4(v1v[4], v1v[5], v1v[6], v1v[7]);
        float4* o2 = (float4*)(g_F1 + (size_t)i * 4096 + (x2 * 16 + y2) * 16 +
                               hs * 8);
        o2[0] = make_float4(v2v[0], v2v[1], v2v[2], v2v[3]);
        o2[1] = make_float4(v2v[4], v2v[5], v2v[6], v2v[7]);
    }
#pragma unroll
    for (int hh = 0; hh < 8; ++hh) {
#pragma unroll
        for (int o = 16; o; o >>= 1)
            g8[hh] += __shfl_xor_sync(0xffffffffu, g8[hh], o);
    }
    const int wid = tid >> 5, lane = tid & 31;
    if (lane == 0) {
#pragma unroll
        for (int hh = 0; hh < 8; ++hh) sm.red[wid][hh] = g8[hh];
    }
    __syncthreads();
    if (tid < 16) {
        int hs2 = tid >> 3, hh = tid & 7;
        float s = sm.red[hs2 * 4 + 0][hh] + sm.red[hs2 * 4 + 1][hh] +
                  sm.red[hs2 * 4 + 2][hh] + sm.red[hs2 * 4 + 3][hh];
        atomicAdd(&g_gsum[16 + hs2 * 8 + hh], (double)s);
    }
}

// ---------------- kernel 4: layer-2 step (direct-LDG gathers) ---------------
__global__ __launch_bounds__(1024, 1) void step2_kernel(
    const float* __restrict__ Wg, const float* __restrict__ bg) {
    extern __shared__ char smraw[];
    Sm2* sm = reinterpret_cast<Sm2*>(smraw);
    const int i = blockIdx.x;
    const int tid = threadIdx.x;
    const int g = tid >> 8, t = tid & 255;
    const int a = t >> 4, c2 = (t & 15) >> 1, hb = t & 1;

    if (tid < 16) sm->nbrs_i[tid] = g_nbrs[i * 16 + tid];
    if (tid < 768) {
        int kp = tid >> 4, h = tid & 15, arr = kp >> 3, cc = (kp & 7) * 2;
        const float* wb = Wg + h * 288 + arr * 32 + cc;
        sm->Wp[tid] = make_float4(wb[0], wb[1], wb[16], wb[17]);
    }
    for (int idx = tid; idx < 1536; idx += 1024) {
        int cci = idx >> 4, h = idx & 15;
        sm->Wvt[idx] = Wg[h * 288 + 192 + cci];
    }
    if (tid >= 768 && tid < 784) sm->bb[tid - 768] = bg[tid - 768];
    __syncthreads();
    if (tid < 256) {
        int m = tid >> 4, aa = tid & 15;
        sm->nbrs_j[m][aa] = g_nbrs[sm->nbrs_i[m] * 16 + aa];
    }
    __syncthreads();
    if (tid < 256) {
        int m = tid >> 4, aa = tid & 15;
        int tgt = sm->nbrs_i[aa];
        int p = -1;
#pragma unroll
        for (int q = 0; q < 16; ++q)
            if (sm->nbrs_j[m][q] == tgt) p = q;
        sm->pi[m][aa] = p;
    }
    __syncthreads();

    // ---------------- Phase A: barrier-free, gathers straight from L1/L2 ----
    float2 s0r2[8];
#pragma unroll
    for (int k = 0; k < 8; ++k) s0r2[k] = make_float2(0.f, 0.f);
    float2 v1a = make_float2(0.f, 0.f), v2a = make_float2(0.f, 0.f);
    float* A1 = sm->Asp + c2 * PS;

#pragma unroll
    for (int iter = 0; iter < 4; ++iter) {
        const int m = iter * 4 + g;
        const int j = sm->nbrs_i[m];
        const float* Fj = g_F1 + (size_t)j * 4096;
        const int pa = sm->pi[m][a];
        const int pm = sm->pi[m][m];
        int4 qA = *(const int4*)&sm->pi[m][hb * 8];
        int4 qB = *(const int4*)&sm->pi[m][hb * 8 + 4];
        const int pbs[8] = {qA.x, qA.y, qA.z, qA.w, qB.x, qB.y, qB.z, qB.w};
        const float* tr = Fj + pa * 256 + 2 * c2;
        float2 rs = make_float2(0.f, 0.f);
#pragma unroll
        for (int k = 0; k < 8; ++k) {
            int pb = pbs[k];
            float2 v = make_float2(0.f, 0.f);
            if (pa >= 0 && pb >= 0) v = *(const float2*)(tr + pb * 16);
            s0r2[k].x += v.x; s0r2[k].y += v.y;
            rs.x += v.x; rs.y += v.y;
            if (a == m)  // d0[m][b] = T[m][b]
                *(float2*)(A1 + 3 * ARRF + swzf(m, hb * 8 + k) * 2) = v;
        }
        {  // d1, d2 via direct loads (dedup across hb)
            float2 dv1 = make_float2(0.f, 0.f), dv2 = make_float2(0.f, 0.f);
            if (pa >= 0) {
                if (hb == (a >> 3)) dv2 = *(const float2*)(tr + pa * 16);
                if (hb == (m >> 3) && pm >= 0)
                    dv1 = *(const float2*)(tr + pm * 16);
            }
            if (hb == (a >> 3))
                *(float2*)(A1 + 5 * ARRF + swzf(m, a) * 2) = dv2;
            if (hb == (m >> 3))
                *(float2*)(A1 + 4 * ARRF + swzf(m, a) * 2) = dv1;
        }
        rs.x += __shfl_xor_sync(0xffffffffu, rs.x, 1);
        rs.y += __shfl_xor_sync(0xffffffffu, rs.y, 1);
        if (hb == 0) *(float2*)(A1 + 2 * ARRF + swzf(m, a) * 2) = rs;
        v1a.x += rs.x; v1a.y += rs.y;
        // column sums (thread plays b = a)
        const float* tc = Fj + pa * 16 + 2 * c2;
        float2 cs = make_float2(0.f, 0.f);
        if (pa >= 0) {
#pragma unroll
            for (int k = 0; k < 8; ++k) {
                int pa2 = pbs[k];
                if (pa2 >= 0) {
                    float2 v = *(const float2*)(tc + pa2 * 256);
                    cs.x += v.x; cs.y += v.y;
                }
            }
        }
        cs.x += __shfl_xor_sync(0xffffffffu, cs.x, 1);
        cs.y += __shfl_xor_sync(0xffffffffu, cs.y, 1);
        if (hb == 0) *(float2*)(A1 + 1 * ARRF + swzf(m, a) * 2) = cs;
        v2a.x += cs.x; v2a.y += cs.y;
    }

    // stage s0 + v partials
    {
        float* stg = sm->P + g * 4224;
#pragma unroll
        for (int k = 0; k < 8; ++k)
            *(float2*)(stg + a * 264 + (hb * 8 + k) * 16 + 2 * c2) = s0r2[k];
        if (hb == 0) {
            *(float2*)(&sm->v1p[g][a * 16 + 2 * c2]) = v1a;
            *(float2*)(&sm->v2p[g][a * 16 + 2 * c2]) = v2a;
        }
    }
    __syncthreads();
    if (tid < 256) {  // v0[m][c] = sum_a s2[m][a][c]
        int m = tid >> 4, cx = tid & 15;
        const float* s2b = sm->Asp + 2 * ARRF + (cx >> 1) * PS + (cx & 1);
        float s = 0.f;
#pragma unroll
        for (int a2 = 0; a2 < 16; ++a2) s += s2b[swzf(m, a2) * 2];
        sm->v0[m * 16 + cx] = s;
    }
#pragma unroll
    for (int p = 0; p < 4; ++p) {  // combine s0 -> Asp[0]
        int idx = tid + p * 1024;
        int a2 = idx >> 8, b2 = (idx >> 4) & 15, cx = idx & 15;
        int off = a2 * 264 + b2 * 16 + cx;
        float s = sm->P[off] + sm->P[4224 + off] + sm->P[8448 + off] +
                  sm->P[12672 + off];
        sm->Asp[(cx >> 1) * PS + swzf(a2, b2) * 2 + (cx & 1)] = s;
    }
    if (tid < 256) {
        sm->v1s[tid] = sm->v1p[0][tid] + sm->v1p[1][tid] + sm->v1p[2][tid] +
                       sm->v1p[3][tid];
        sm->v2s[tid] = sm->v2p[0][tid] + sm->v2p[1][tid] + sm->v2p[2][tid] +
                       sm->v2p[3][tid];
    }
    __syncthreads();

    // ---------------- Phase B ------------------------------------------------
    if (tid < 512) {  // rowt / colt from v-blocks
        int half = tid >> 8, al = (tid >> 4) & 15, h = tid & 15;
        float acc = 0.f;
#pragma unroll
        for (int cc = 0; cc < 16; ++cc) {
            float a0 = sm->v0[al * 16 + cc];
            float a1 = sm->v1s[al * 16 + cc];
            float a2v = sm->v2s[al * 16 + cc];
            const float* wv = &sm->Wvt[(half * 16 + cc) * 16 + h];
            acc += a0 * wv[0] + a1 * wv[512] + a2v * wv[1024];
        }
        (half ? sm->colt : sm->rowt)[al * 16 + h] = acc;
    }

    const int sec = tid >> 7, u = tid & 127;
    const int ks = sec >> 1, hs = sec & 1;
    int x1, y1, x2, y2;
    bool diag;
    unrank(u, x1, y1, x2, y2, diag);
    const int sw1 = swzf(x1, y1), sw2 = swzf(x2, y2);
    const int pos1 = x1 * 16 + y1, pos2 = x2 * 16 + y2;

    unsigned long long acc1[8], acc2[8];
#pragma unroll
    for (int h = 0; h < 8; ++h) { acc1[h] = 0ull; acc2[h] = 0ull; }
    unsigned wadr = sptr(sm->Wp) + ((ks * 12) * 16 + hs * 8) * 16;

#pragma unroll 4
    for (int uu = 0; uu < 12; ++uu) {
        int kp = ks * 12 + uu;
        const float* pl = sm->Asp + (kp >> 3) * ARRF + (kp & 7) * PS;
        unsigned long long va = *(const unsigned long long*)(pl + sw1 * 2);
        unsigned long long vb = *(const unsigned long long*)(pl + sw2 * 2);
        unsigned long long t1 = diag ? va : vb;
        unsigned long long t2 = diag ? vb : va;
#pragma unroll
        for (int hh = 0; hh < 8; ++hh) {
            unsigned long long we, wo;
            LDW2(we, wo, wadr + uu * 256 + hh * 16);
            FMA2(acc1[hh], va, we);
            FMA2(acc1[hh], t1, wo);
            FMA2(acc2[hh], vb, we);
            FMA2(acc2[hh], t2, wo);
        }
    }
    {
        float* p1 = sm->P + (sec * 256 + pos1) * 8;
        float* p2 = sm->P + (sec * 256 + pos2) * 8;
        *(float4*)p1 = make_float4(sum2(acc1[0]), sum2(acc1[1]), sum2(acc1[2]),
                                   sum2(acc1[3]));
        *(float4*)(p1 + 4) = make_float4(sum2(acc1[4]), sum2(acc1[5]),
                                         sum2(acc1[6]), sum2(acc1[7]));
        *(float4*)p2 = make_float4(sum2(acc2[0]), sum2(acc2[1]), sum2(acc2[2]),
                                   sum2(acc2[3]));
        *(float4*)(p2 + 4) = make_float4(sum2(acc2[4]), sum2(acc2[5]),
                                         sum2(acc2[6]), sum2(acc2[7]));
    }
    __syncthreads();

    // final combine + g reduction (no F output in layer 2)
    const int pos = tid >> 2, hq = tid & 3;
    const int alf = pos >> 4, bef = pos & 15;
    const int hsf = hq >> 1, hof = (hq & 1) * 4;
    float4 q0 = *(const float4*)(sm->P + ((0 + hsf) * 256 + pos) * 8 + hof);
    float4 q1 = *(const float4*)(sm->P + ((2 + hsf) * 256 + pos) * 8 + hof);
    float4 q2 = *(const float4*)(sm->P + ((4 + hsf) * 256 + pos) * 8 + hof);
    float4 q3 = *(const float4*)(sm->P + ((6 + hsf) * 256 + pos) * 8 + hof);
    float4 rw = *(const float4*)(&sm->rowt[alf * 16 + hq * 4]);
    float4 cl = *(const float4*)(&sm->colt[bef * 16 + hq * 4]);
    float4 bv = *(const float4*)(&sm->bb[hq * 4]);
    float vals[4];
    vals[0] = fmaxf(q0.x + q1.x + q2.x + q3.x + rw.x + cl.x + bv.x, 0.f);
    vals[1] = fmaxf(q0.y + q1.y + q2.y + q3.y + rw.y + cl.y + bv.y, 0.f);
    vals[2] = fmaxf(q0.z + q1.z + q2.z + q3.z + rw.z + cl.z + bv.z, 0.f);
    vals[3] = fmaxf(q0.w + q1.w + q2.w + q3.w + rw.w + cl.w + bv.w, 0.f);

    const int w = tid >> 5, lane = tid & 31;
#pragma unroll
    for (int k2 = 0; k2 < 4; ++k2) {
        float v = vals[k2];
        v += __shfl_xor_sync(0xffffffffu, v, 4);
        v += __shfl_xor_sync(0xffffffffu, v, 8);
        v += __shfl_xor_sync(0xffffffffu, v, 16);
        vals[k2] = v;
    }
    if (lane < 4) {
#pragma unroll
        for (int k2 = 0; k2 < 4; ++k2) sm->red[w * 16 + lane * 4 + k2] = vals[k2];
    }
    __syncthreads();
    if (tid < 16) {
        float s = 0.f;
#pragma unroll
        for (int w2 = 0; w2 < 32; ++w2) s += sm->red[w2 * 16 + tid];
        atomicAdd(&g_gsum[32 + tid], (double)s);
    }
}

// ---------------- kernel 5: final dot with fc --------------------------------
__global__ void final_kernel(const float* __restrict__ fc_w,
                             const float* __restrict__ fc_b,
                             float* __restrict__ out) {
    if (threadIdx.x == 0) {
        double s = (double)fc_b[0];
#pragma unroll
        for (int c = 0; c < 48; ++c) s += g_gsum[c] * (double)fc_w[c];
        out[0] = (float)s;
    }
}

// ---------------- host entry --------------------------------------------------
extern "C" void kernel_launch(void* const* d_in, const int* in_sizes, int n_in,
                              void* d_out, int out_size) {
    const float* X   = (const float*)d_in[0];
    const float* adj = (const float*)d_in[1];
    const float* W1  = (const float*)d_in[2];
    const float* b1  = (const float*)d_in[3];
    const float* W2  = (const float*)d_in[4];
    const float* b2  = (const float*)d_in[5];
    const float* fcw = (const float*)d_in[6];
    const float* fcb = (const float*)d_in[7];
    float* out = (float*)d_out;

    const int SMEM2 = (int)sizeof(Sm2);
    cudaFuncSetAttribute(step2_kernel,
                         cudaFuncAttributeMaxDynamicSharedMemorySize, SMEM2);

    nbrs_kernel<<<250, 256>>>(adj);
    f0sum_kernel<<<125, 256>>>(X);
    step1_kernel<<<NN, 256>>>(X, W1, b1);
    step2_kernel<<<NN, 1024, SMEM2>>>(W2, b2);
    final_kernel<<<1, 32>>>(fcw, fcb, out);
}